// round 2
// baseline (speedup 1.0000x reference)
#include <cuda_runtime.h>

#define K1v 16
#define BATCH 16
#define CH 32
#define NP 4096
#define EDG (NP*K1v)
#define BT 128
#define INVC 0.9999950000374997f  // 1/sqrt(1+1e-5)

// Scratch (no cudaMalloc allowed)
__device__ int   g_idx[BATCH*NP*K1v];     // 4 MB
__device__ float g_featT[BATCH*NP*CH];    // 8 MB: features transposed to [b][p][c]

// ---------------------------------------------------------------------------
// idx default init: idx0[b,p,j] = P - K1 + j
// ---------------------------------------------------------------------------
__global__ void init_idx_kernel() {
    int t = blockIdx.x * blockDim.x + threadIdx.x;
    if (t < BATCH*NP*K1v) {
        int j = t & (K1v - 1);
        g_idx[t] = NP - K1v + j;
    }
}

// ---------------------------------------------------------------------------
// General get_edges: per-batch inclusive scans (cummax of change index,
// prefix-OR of broken), then scatter tgt into idx[b, pf, j].
// One block per batch, 1024 threads, 64 elems/thread.
// ---------------------------------------------------------------------------
__global__ void edge_kernel(const int* __restrict__ ef) {
    const int b = blockIdx.x;
    const int t = threadIdx.x;
    const int CHUNK = EDG / 1024;  // 64
    const int* __restrict__ pf = ef + (size_t)b * 2 * EDG;
    const int* __restrict__ tg = pf + EDG;

    const int e0 = t * CHUNK;

    // pass 1: per-chunk aggregates
    int prev = (e0 > 0) ? pf[e0 - 1] : 0;
    int vmax = 0, vor = 0;
    for (int r = 0; r < CHUNK; r++) {
        int e = e0 + r;
        int v = pf[e];
        bool change = (e > 0) && (v != prev);
        if (change) { vmax = e; vor |= (v == 0); }
        prev = v;
    }

    __shared__ int smax[1024];
    __shared__ int sor[1024];
    smax[t] = vmax; sor[t] = vor;
    __syncthreads();
    for (int off = 1; off < 1024; off <<= 1) {
        int m = smax[t], o = sor[t];
        if (t >= off) { int m2 = smax[t - off]; int o2 = sor[t - off]; m = m > m2 ? m : m2; o |= o2; }
        __syncthreads();
        smax[t] = m; sor[t] = o;
        __syncthreads();
    }
    int runmax = (t > 0) ? smax[t - 1] : 0;
    int brok   = (t > 0) ? sor[t - 1]  : 0;

    // pass 2: rescan with carry-in, scatter valid entries
    prev = (e0 > 0) ? pf[e0 - 1] : 0;
    for (int r = 0; r < CHUNK; r++) {
        int e = e0 + r;
        int v = pf[e];
        bool change = (e > 0) && (v != prev);
        if (change) { runmax = e; brok |= (v == 0); }
        prev = v;
        int j = e - runmax;
        if (!brok && j < K1v) {
            unsigned row = (unsigned)v;
            if (row < (unsigned)NP)
                g_idx[((size_t)b * NP + row) * K1v + j] = tg[e];
        }
    }
}

// ---------------------------------------------------------------------------
// Transpose features (B,C,P) -> (B,P,C) so neighbor gathers are one 128B line.
// ---------------------------------------------------------------------------
__global__ void transpose_kernel(const float* __restrict__ f) {
    __shared__ float tile[32][33];
    int b  = blockIdx.y;
    int p0 = blockIdx.x * 32;
    int tx = threadIdx.x, ty = threadIdx.y;  // (32, 8)
    #pragma unroll
    for (int i = 0; i < 32; i += 8)
        tile[ty + i][tx] = f[((size_t)b * CH + ty + i) * NP + p0 + tx];
    __syncthreads();
    #pragma unroll
    for (int i = 0; i < 32; i += 8)
        g_featT[((size_t)b * NP + p0 + ty + i) * CH + tx] = tile[tx][ty + i];
}

// ---------------------------------------------------------------------------
// Fused main kernel: one thread per (b,p). BT=128 threads/block.
// Persistent regs: cf[32], pb0[32].  fts lives in SHARED ([o][tid], no conflict)
// to avoid register spill. Weights in shared, broadcast LDS.128.
// Dynamic shared layout (floats):
//   [0      ,1024)  W0 low  half (center cols)   [o*32+c]
//   [1024   ,2048)  W0 high half (neighbor cols) [o*32+c]
//   [2048   ,3072)  W1 [o*32+c]
//   [3072   ,5120)  W2 [o*32+c]  (64x32)
//   [5120   ,7168)  SW [o*32+c]  (64x32)
//   [7168   ,7296)  ss0[32], sb0[32], ss1[32], sb1[32]
//   [7296   ,7552)  ss2[64], sb2[64], ssc[64], sbc[64]
//   [7552   ,15744) sfts [64][BT]
// ---------------------------------------------------------------------------
#define SMEM_FLOATS 15744

__global__ void __launch_bounds__(BT) main_kernel(
    const float* __restrict__ W0, const float* __restrict__ g0, const float* __restrict__ bb0,
    const float* __restrict__ W1, const float* __restrict__ g1, const float* __restrict__ bb1,
    const float* __restrict__ W2, const float* __restrict__ g2, const float* __restrict__ bb2,
    const float* __restrict__ SW, const float* __restrict__ sg, const float* __restrict__ sb,
    float* __restrict__ out)
{
    extern __shared__ float sm[];
    float* sW0l = sm;
    float* sW0h = sm + 1024;
    float* sW1  = sm + 2048;
    float* sW2  = sm + 3072;
    float* sSW  = sm + 5120;
    float* ss0  = sm + 7168;
    float* sb0  = sm + 7200;
    float* ss1  = sm + 7232;
    float* sb1  = sm + 7264;
    float* ss2  = sm + 7296;
    float* sb2  = sm + 7360;
    float* ssc  = sm + 7424;
    float* sbc  = sm + 7488;
    float* sfts = sm + 7552;

    const int tid = threadIdx.x;
    for (int i = tid; i < 32 * 64; i += BT) {
        int o = i >> 6, c = i & 63;
        float w = W0[i];
        if (c < 32) sW0l[o * 32 + c] = w; else sW0h[o * 32 + (c - 32)] = w;
    }
    for (int i = tid; i < 32 * 32; i += BT) sW1[i] = W1[i];
    for (int i = tid; i < 64 * 32; i += BT) sW2[i] = W2[i];
    for (int i = tid; i < 64 * 32; i += BT) sSW[i] = SW[i];
    if (tid < 32) { ss0[tid] = g0[tid] * INVC; sb0[tid] = bb0[tid];
                    ss1[tid] = g1[tid] * INVC; sb1[tid] = bb1[tid]; }
    if (tid < 64) { ss2[tid] = g2[tid] * INVC; sb2[tid] = bb2[tid];
                    ssc[tid] = sg[tid] * INVC; sbc[tid] = sb[tid]; }
    // zero my fts column
    #pragma unroll
    for (int o = 0; o < 64; o++) sfts[o * BT + tid] = 0.f;
    __syncthreads();

    const int gp = blockIdx.x * BT + tid;
    const int b = gp >> 12;       // / 4096
    const int p = gp & (NP - 1);

    const float* __restrict__ fT = g_featT + (size_t)b * NP * CH;

    float cf[32];
    {
        const float* cfp = fT + (size_t)p * CH;
        #pragma unroll
        for (int i = 0; i < 32; i++) cf[i] = cfp[i];
    }

    float pb0[32];
    #pragma unroll
    for (int o = 0; o < 32; o++) {
        float a = 0.f;
        #pragma unroll
        for (int c = 0; c < 32; c++) a = fmaf(sW0l[o * 32 + c], cf[c], a);
        pb0[o] = fmaf(a, ss0[o], sb0[o]);
    }

    const int* __restrict__ ip = g_idx + ((size_t)b * NP + p) * K1v;

    #pragma unroll 1
    for (int k = 0; k < K1v; k++) {
        int q = ip[k];
        float xh[32];
        {
            const float* qp = fT + (size_t)q * CH;
            #pragma unroll
            for (int i = 0; i < 32; i++) xh[i] = qp[i] - cf[i];
        }
        float h0[32];
        #pragma unroll
        for (int o = 0; o < 32; o++) {
            float a = 0.f;
            #pragma unroll
            for (int c = 0; c < 32; c++) a = fmaf(sW0h[o * 32 + c], xh[c], a);
            h0[o] = fmaxf(fmaf(a, ss0[o], pb0[o]), 0.f);
        }
        float h1[32];
        #pragma unroll
        for (int o = 0; o < 32; o++) {
            float a = 0.f;
            #pragma unroll
            for (int c = 0; c < 32; c++) a = fmaf(sW1[o * 32 + c], h0[c], a);
            h1[o] = fmaxf(fmaf(a, ss1[o], sb1[o]), 0.f);
        }
        #pragma unroll
        for (int o = 0; o < 64; o++) {
            float a = 0.f;
            #pragma unroll
            for (int c = 0; c < 32; c++) a = fmaf(sW2[o * 32 + c], h1[c], a);
            float v = fmaxf(fmaf(a, ss2[o], sb2[o]), 0.f);
            sfts[o * BT + tid] += v;
        }
    }

    // shortcut + mean + final relu; stores coalesced per output channel
    float* __restrict__ ob = out + (size_t)b * 64 * NP + p;
    #pragma unroll
    for (int o = 0; o < 64; o++) {
        float a = 0.f;
        #pragma unroll
        for (int c = 0; c < 32; c++) a = fmaf(sSW[o * 32 + c], cf[c], a);
        float sc = fmaf(a, ssc[o], sbc[o]);
        ob[(size_t)o * NP] = fmaxf(sc + sfts[o * BT + tid] * (1.0f / 16.0f), 0.f);
    }
}

// ---------------------------------------------------------------------------
extern "C" void kernel_launch(void* const* d_in, const int* in_sizes, int n_in,
                              void* d_out, int out_size)
{
    (void)in_sizes; (void)n_in; (void)out_size;
    const float* features = (const float*)d_in[1];
    const int*   ef       = (const int*)d_in[2];

    static bool attr_set = false;
    if (!attr_set) {
        cudaFuncSetAttribute(main_kernel,
                             cudaFuncAttributeMaxDynamicSharedMemorySize,
                             SMEM_FLOATS * (int)sizeof(float));
        attr_set = true;
    }

    init_idx_kernel<<<(BATCH*NP*K1v + 255) / 256, 256>>>();
    edge_kernel<<<BATCH, 1024>>>(ef);
    {
        dim3 tb(32, 8), tg(NP / 32, BATCH);
        transpose_kernel<<<tg, tb>>>(features);
    }
    main_kernel<<<(BATCH * NP) / BT, BT, SMEM_FLOATS * sizeof(float)>>>(
        (const float*)d_in[3],  (const float*)d_in[4],  (const float*)d_in[5],
        (const float*)d_in[6],  (const float*)d_in[7],  (const float*)d_in[8],
        (const float*)d_in[9],  (const float*)d_in[10], (const float*)d_in[11],
        (const float*)d_in[12], (const float*)d_in[13], (const float*)d_in[14],
        (float*)d_out);
}

// round 3
// speedup vs baseline: 1.2306x; 1.2306x over previous
#include <cuda_runtime.h>

#define K1v 16
#define BATCH 16
#define CH 32
#define NP 4096
#define EDG (NP*K1v)
#define INVC 0.9999950000374997f  // 1/sqrt(1+1e-5)

// Scratch (no cudaMalloc allowed)
__device__ int   g_idx[BATCH*NP*K1v];     // 4 MB
__device__ float g_featT[BATCH*NP*CH];    // 8 MB: features transposed to [b][p][c]

typedef unsigned long long u64;

__device__ __forceinline__ u64 fma2(u64 a, u64 b, u64 c) {
    u64 d;
    asm("fma.rn.f32x2 %0, %1, %2, %3;" : "=l"(d) : "l"(a), "l"(b), "l"(c));
    return d;
}
__device__ __forceinline__ u64 pack2(float x, float y) {
    u64 d;
    asm("mov.b64 %0, {%1, %2};" : "=l"(d) : "f"(x), "f"(y));
    return d;
}
__device__ __forceinline__ void unpack2(u64 v, float& x, float& y) {
    asm("mov.b64 {%0, %1}, %2;" : "=f"(x), "=f"(y) : "l"(v));
}

// ---------------------------------------------------------------------------
__global__ void init_idx_kernel() {
    int t = blockIdx.x * blockDim.x + threadIdx.x;
    if (t < BATCH*NP*K1v) {
        int j = t & (K1v - 1);
        g_idx[t] = NP - K1v + j;
    }
}

// ---------------------------------------------------------------------------
// General get_edges scan + scatter (one block per batch).
// ---------------------------------------------------------------------------
__global__ void edge_kernel(const int* __restrict__ ef) {
    const int b = blockIdx.x;
    const int t = threadIdx.x;
    const int CHUNK = EDG / 1024;  // 64
    const int* __restrict__ pf = ef + (size_t)b * 2 * EDG;
    const int* __restrict__ tg = pf + EDG;

    const int e0 = t * CHUNK;

    int prev = (e0 > 0) ? pf[e0 - 1] : 0;
    int vmax = 0, vor = 0;
    for (int r = 0; r < CHUNK; r++) {
        int e = e0 + r;
        int v = pf[e];
        bool change = (e > 0) && (v != prev);
        if (change) { vmax = e; vor |= (v == 0); }
        prev = v;
    }

    __shared__ int smax[1024];
    __shared__ int sor[1024];
    smax[t] = vmax; sor[t] = vor;
    __syncthreads();
    for (int off = 1; off < 1024; off <<= 1) {
        int m = smax[t], o = sor[t];
        if (t >= off) { int m2 = smax[t - off]; int o2 = sor[t - off]; m = m > m2 ? m : m2; o |= o2; }
        __syncthreads();
        smax[t] = m; sor[t] = o;
        __syncthreads();
    }
    int runmax = (t > 0) ? smax[t - 1] : 0;
    int brok   = (t > 0) ? sor[t - 1]  : 0;

    prev = (e0 > 0) ? pf[e0 - 1] : 0;
    for (int r = 0; r < CHUNK; r++) {
        int e = e0 + r;
        int v = pf[e];
        bool change = (e > 0) && (v != prev);
        if (change) { runmax = e; brok |= (v == 0); }
        prev = v;
        int j = e - runmax;
        if (!brok && j < K1v) {
            unsigned row = (unsigned)v;
            if (row < (unsigned)NP)
                g_idx[((size_t)b * NP + row) * K1v + j] = tg[e];
        }
    }
}

// ---------------------------------------------------------------------------
// Transpose features (B,C,P) -> (B,P,C): neighbor gather = one 128B row.
// ---------------------------------------------------------------------------
__global__ void transpose_kernel(const float* __restrict__ f) {
    __shared__ float tile[32][33];
    int b  = blockIdx.y;
    int p0 = blockIdx.x * 32;
    int tx = threadIdx.x, ty = threadIdx.y;  // (32, 8)
    #pragma unroll
    for (int i = 0; i < 32; i += 8)
        tile[ty + i][tx] = f[((size_t)b * CH + ty + i) * NP + p0 + tx];
    __syncthreads();
    #pragma unroll
    for (int i = 0; i < 32; i += 8)
        g_featT[((size_t)b * NP + p0 + ty + i) * CH + tx] = tile[tx][ty + i];
}

// ---------------------------------------------------------------------------
// Main kernel: register-tiled warp GEMM over 16 points (=256 neighbor rows)
// per CTA of 128 threads. f32x2 packed FMA. All activations staged in smem.
//
// Dynamic smem layout (float offsets):
//   0      sWt0l [32c][32o]   (W0 center half, transposed)
//   1024   sWt0h [32c][32o]   (W0 neighbor half)
//   2048   sWt1  [32c][32o]
//   3072   sWt2  [32c][64o]
//   5120   sWtc  [32c][64o]   (shortcut)
//   7168   ss0[32] sb0[32] ss1[32] sb1[32]
//   7296   ss2[64] sb2[64] ssc[64] sbc[64]
//   7552   CF   [32c][16pt]
//   8064   pb0s [32o][16pt]
//   8576   red  [64o][16pt][2]
//   10624  XA   [32][256]
//   18816  XB   [32][256]
//   27008  total floats (105.5 KB)
// ---------------------------------------------------------------------------
#define TP 16
#define RR 256
#define SMEM_FLOATS 27008

__global__ void __launch_bounds__(128) main_kernel(
    const float* __restrict__ W0, const float* __restrict__ g0, const float* __restrict__ bb0,
    const float* __restrict__ W1, const float* __restrict__ g1, const float* __restrict__ bb1,
    const float* __restrict__ W2, const float* __restrict__ g2, const float* __restrict__ bb2,
    const float* __restrict__ SW, const float* __restrict__ sg, const float* __restrict__ sb,
    float* __restrict__ out)
{
    extern __shared__ float sm[];
    float* sWt0l = sm;
    float* sWt0h = sm + 1024;
    float* sWt1  = sm + 2048;
    float* sWt2  = sm + 3072;
    float* sWtc  = sm + 5120;
    float* ss0   = sm + 7168;
    float* sb0   = sm + 7200;
    float* ss1   = sm + 7232;
    float* sb1   = sm + 7264;
    float* ss2   = sm + 7296;
    float* sb2   = sm + 7360;
    float* ssc   = sm + 7424;
    float* sbc   = sm + 7488;
    float* CF    = sm + 7552;
    float* pb0s  = sm + 8064;
    float* red   = sm + 8576;
    float* XA    = sm + 10624;
    float* XB    = sm + 18816;

    const int tid  = threadIdx.x;
    const int base = blockIdx.x * TP;      // global point base
    const int b    = base >> 12;
    const int p0   = base & (NP - 1);

    // ---- stage weights (transposed [c][o]) and scales ----
    for (int i = tid; i < 2048; i += 128) {        // W0: (32o, 64c)
        int o = i >> 6, c = i & 63;
        float w = W0[i];
        if (c < 32) sWt0l[c * 32 + o] = w;
        else        sWt0h[(c - 32) * 32 + o] = w;
    }
    for (int i = tid; i < 1024; i += 128) {        // W1: (32o, 32c)
        int o = i >> 5, c = i & 31;
        sWt1[c * 32 + o] = W1[i];
    }
    for (int i = tid; i < 2048; i += 128) {        // W2: (64o, 32c)
        int o = i >> 5, c = i & 31;
        sWt2[c * 64 + o] = W2[i];
    }
    for (int i = tid; i < 2048; i += 128) {        // SW: (64o, 32c)
        int o = i >> 5, c = i & 31;
        sWtc[c * 64 + o] = SW[i];
    }
    if (tid < 32) { ss0[tid] = g0[tid] * INVC; sb0[tid] = bb0[tid];
                    ss1[tid] = g1[tid] * INVC; sb1[tid] = bb1[tid]; }
    else if (tid < 96) { int o = tid - 32;
                    ss2[o] = g2[o] * INVC; sb2[o] = bb2[o];
                    ssc[o] = sg[o] * INVC; sbc[o] = sb[o]; }

    const float* __restrict__ fT = g_featT + (size_t)b * NP * CH;

    // ---- stage XH rows: XA[c][r], r = pt*16 + k ----
    #pragma unroll
    for (int rr = 0; rr < 2; rr++) {
        int r   = tid + rr * 128;
        int ptl = r >> 4;
        int k   = r & 15;
        int p   = p0 + ptl;
        int q   = g_idx[(((size_t)b * NP + p) << 4) + k];
        const float4* qp = (const float4*)(fT + (size_t)q * CH);
        const float4* pp = (const float4*)(fT + (size_t)p * CH);
        #pragma unroll
        for (int i = 0; i < 8; i++) {
            float4 a = qp[i], v = pp[i];
            XA[(4*i+0) * RR + r] = a.x - v.x;
            XA[(4*i+1) * RR + r] = a.y - v.y;
            XA[(4*i+2) * RR + r] = a.z - v.z;
            XA[(4*i+3) * RR + r] = a.w - v.w;
        }
    }

    // ---- stage CF[c][pt] ----
    if (tid < TP) {
        const float4* pp = (const float4*)(fT + (size_t)(p0 + tid) * CH);
        #pragma unroll
        for (int i = 0; i < 8; i++) {
            float4 v = pp[i];
            CF[(4*i+0) * TP + tid] = v.x;
            CF[(4*i+1) * TP + tid] = v.y;
            CF[(4*i+2) * TP + tid] = v.z;
            CF[(4*i+3) * TP + tid] = v.w;
        }
    }
    __syncthreads();

    // ---- pb0[o][pt] = (W0l . cf)*ss0 + sb0  (threads 0..63) ----
    if (tid < 64) {
        int og = (tid & 3) * 8;
        int pt = tid >> 2;
        float a[8];
        #pragma unroll
        for (int j = 0; j < 8; j++) a[j] = 0.f;
        #pragma unroll
        for (int c = 0; c < 32; c++) {
            float4 w0 = *(const float4*)(sWt0l + c * 32 + og);
            float4 w1 = *(const float4*)(sWt0l + c * 32 + og + 4);
            float cf = CF[c * TP + pt];
            a[0] = fmaf(w0.x, cf, a[0]); a[1] = fmaf(w0.y, cf, a[1]);
            a[2] = fmaf(w0.z, cf, a[2]); a[3] = fmaf(w0.w, cf, a[3]);
            a[4] = fmaf(w1.x, cf, a[4]); a[5] = fmaf(w1.y, cf, a[5]);
            a[6] = fmaf(w1.z, cf, a[6]); a[7] = fmaf(w1.w, cf, a[7]);
        }
        #pragma unroll
        for (int j = 0; j < 8; j++)
            pb0s[(og + j) * TP + pt] = fmaf(a[j], ss0[og + j], sb0[og + j]);
    }
    __syncthreads();

    // ---- warp/lane tiling ----
    const int warp = tid >> 5;
    const int lane = tid & 31;
    const int oi   = lane >> 3;        // 0..3  -> o block of 8
    const int ri   = lane & 7;         // 0..7  -> r block of 8
    const int o0   = oi * 8;
    const int r0   = warp * 64 + ri * 8;
    const int ptl  = r0 >> 4;          // all 8 r's share one point
    const int half = ri & 1;

    // ================= GEMM1: H0 = relu(ss0*(W0h . XH) + pb0) =================
    {
        u64 acc[8][4];
        #pragma unroll
        for (int o = 0; o < 8; o++)
            #pragma unroll
            for (int j = 0; j < 4; j++) acc[o][j] = 0ull;

        #pragma unroll
        for (int k = 0; k < 32; k++) {
            float4 w0 = *(const float4*)(sWt0h + k * 32 + o0);
            float4 w1 = *(const float4*)(sWt0h + k * 32 + o0 + 4);
            float4 xa = *(const float4*)(XA + k * RR + r0);
            float4 xb = *(const float4*)(XA + k * RR + r0 + 4);
            u64 xp0 = pack2(xa.x, xa.y), xp1 = pack2(xa.z, xa.w);
            u64 xp2 = pack2(xb.x, xb.y), xp3 = pack2(xb.z, xb.w);
            u64 wd[8] = { pack2(w0.x,w0.x), pack2(w0.y,w0.y), pack2(w0.z,w0.z), pack2(w0.w,w0.w),
                          pack2(w1.x,w1.x), pack2(w1.y,w1.y), pack2(w1.z,w1.z), pack2(w1.w,w1.w) };
            #pragma unroll
            for (int o = 0; o < 8; o++) {
                acc[o][0] = fma2(wd[o], xp0, acc[o][0]);
                acc[o][1] = fma2(wd[o], xp1, acc[o][1]);
                acc[o][2] = fma2(wd[o], xp2, acc[o][2]);
                acc[o][3] = fma2(wd[o], xp3, acc[o][3]);
            }
        }
        #pragma unroll
        for (int oin = 0; oin < 8; oin++) {
            int o = o0 + oin;
            float s  = ss0[o];
            float pb = pb0s[o * TP + ptl];
            float h[8];
            #pragma unroll
            for (int j = 0; j < 4; j++) unpack2(acc[oin][j], h[2*j], h[2*j+1]);
            #pragma unroll
            for (int e = 0; e < 8; e++) h[e] = fmaxf(fmaf(h[e], s, pb), 0.f);
            *(float4*)(XB + o * RR + r0)     = make_float4(h[0],h[1],h[2],h[3]);
            *(float4*)(XB + o * RR + r0 + 4) = make_float4(h[4],h[5],h[6],h[7]);
        }
    }
    __syncthreads();

    // ================= GEMM2: H1 = relu(ss1*(W1 . H0) + sb1) -> XA =================
    {
        u64 acc[8][4];
        #pragma unroll
        for (int o = 0; o < 8; o++)
            #pragma unroll
            for (int j = 0; j < 4; j++) acc[o][j] = 0ull;

        #pragma unroll
        for (int k = 0; k < 32; k++) {
            float4 w0 = *(const float4*)(sWt1 + k * 32 + o0);
            float4 w1 = *(const float4*)(sWt1 + k * 32 + o0 + 4);
            float4 xa = *(const float4*)(XB + k * RR + r0);
            float4 xb = *(const float4*)(XB + k * RR + r0 + 4);
            u64 xp0 = pack2(xa.x, xa.y), xp1 = pack2(xa.z, xa.w);
            u64 xp2 = pack2(xb.x, xb.y), xp3 = pack2(xb.z, xb.w);
            u64 wd[8] = { pack2(w0.x,w0.x), pack2(w0.y,w0.y), pack2(w0.z,w0.z), pack2(w0.w,w0.w),
                          pack2(w1.x,w1.x), pack2(w1.y,w1.y), pack2(w1.z,w1.z), pack2(w1.w,w1.w) };
            #pragma unroll
            for (int o = 0; o < 8; o++) {
                acc[o][0] = fma2(wd[o], xp0, acc[o][0]);
                acc[o][1] = fma2(wd[o], xp1, acc[o][1]);
                acc[o][2] = fma2(wd[o], xp2, acc[o][2]);
                acc[o][3] = fma2(wd[o], xp3, acc[o][3]);
            }
        }
        #pragma unroll
        for (int oin = 0; oin < 8; oin++) {
            int o = o0 + oin;
            float s  = ss1[o];
            float bv = sb1[o];
            float h[8];
            #pragma unroll
            for (int j = 0; j < 4; j++) unpack2(acc[oin][j], h[2*j], h[2*j+1]);
            #pragma unroll
            for (int e = 0; e < 8; e++) h[e] = fmaxf(fmaf(h[e], s, bv), 0.f);
            *(float4*)(XA + o * RR + r0)     = make_float4(h[0],h[1],h[2],h[3]);
            *(float4*)(XA + o * RR + r0 + 4) = make_float4(h[4],h[5],h[6],h[7]);
        }
    }
    __syncthreads();

    // ======== GEMM3: F = relu(ss2*(W2 . H1) + sb2); reduce over neighbors ========
    #pragma unroll 1
    for (int ob = 0; ob < 2; ob++) {
        int o0g = ob * 32 + o0;
        u64 acc[8][4];
        #pragma unroll
        for (int o = 0; o < 8; o++)
            #pragma unroll
            for (int j = 0; j < 4; j++) acc[o][j] = 0ull;

        #pragma unroll
        for (int k = 0; k < 32; k++) {
            float4 w0 = *(const float4*)(sWt2 + k * 64 + o0g);
            float4 w1 = *(const float4*)(sWt2 + k * 64 + o0g + 4);
            float4 xa = *(const float4*)(XA + k * RR + r0);
            float4 xb = *(const float4*)(XA + k * RR + r0 + 4);
            u64 xp0 = pack2(xa.x, xa.y), xp1 = pack2(xa.z, xa.w);
            u64 xp2 = pack2(xb.x, xb.y), xp3 = pack2(xb.z, xb.w);
            u64 wd[8] = { pack2(w0.x,w0.x), pack2(w0.y,w0.y), pack2(w0.z,w0.z), pack2(w0.w,w0.w),
                          pack2(w1.x,w1.x), pack2(w1.y,w1.y), pack2(w1.z,w1.z), pack2(w1.w,w1.w) };
            #pragma unroll
            for (int o = 0; o < 8; o++) {
                acc[o][0] = fma2(wd[o], xp0, acc[o][0]);
                acc[o][1] = fma2(wd[o], xp1, acc[o][1]);
                acc[o][2] = fma2(wd[o], xp2, acc[o][2]);
                acc[o][3] = fma2(wd[o], xp3, acc[o][3]);
            }
        }
        #pragma unroll
        for (int oin = 0; oin < 8; oin++) {
            int o = o0g + oin;
            float s  = ss2[o];
            float bv = sb2[o];
            float partial = 0.f;
            #pragma unroll
            for (int j = 0; j < 4; j++) {
                float v0, v1;
                unpack2(acc[oin][j], v0, v1);
                v0 = fmaxf(fmaf(v0, s, bv), 0.f);
                v1 = fmaxf(fmaf(v1, s, bv), 0.f);
                partial += v0 + v1;
            }
            red[o * 32 + ptl * 2 + half] = partial;
        }
    }
    __syncthreads();

    // ---- shortcut + mean + final relu ----
    {
        int o0s = (tid & 7) * 8;
        int pt  = tid >> 3;
        float a[8];
        #pragma unroll
        for (int j = 0; j < 8; j++) a[j] = 0.f;
        #pragma unroll
        for (int c = 0; c < 32; c++) {
            float4 w0 = *(const float4*)(sWtc + c * 64 + o0s);
            float4 w1 = *(const float4*)(sWtc + c * 64 + o0s + 4);
            float cf = CF[c * TP + pt];
            a[0] = fmaf(w0.x, cf, a[0]); a[1] = fmaf(w0.y, cf, a[1]);
            a[2] = fmaf(w0.z, cf, a[2]); a[3] = fmaf(w0.w, cf, a[3]);
            a[4] = fmaf(w1.x, cf, a[4]); a[5] = fmaf(w1.y, cf, a[5]);
            a[6] = fmaf(w1.z, cf, a[6]); a[7] = fmaf(w1.w, cf, a[7]);
        }
        #pragma unroll
        for (int j = 0; j < 8; j++) {
            int o = o0s + j;
            float fts = (red[o * 32 + pt * 2] + red[o * 32 + pt * 2 + 1]) * (1.0f / 16.0f);
            float v = fmaf(a[j], ssc[o], sbc[o]) + fts;
            out[((size_t)b * 64 + o) * NP + p0 + pt] = fmaxf(v, 0.f);
        }
    }
}

// ---------------------------------------------------------------------------
extern "C" void kernel_launch(void* const* d_in, const int* in_sizes, int n_in,
                              void* d_out, int out_size)
{
    (void)in_sizes; (void)n_in; (void)out_size;
    const float* features = (const float*)d_in[1];
    const int*   ef       = (const int*)d_in[2];

    static bool attr_set = false;
    if (!attr_set) {
        cudaFuncSetAttribute(main_kernel,
                             cudaFuncAttributeMaxDynamicSharedMemorySize,
                             SMEM_FLOATS * (int)sizeof(float));
        attr_set = true;
    }

    init_idx_kernel<<<(BATCH*NP*K1v + 255) / 256, 256>>>();
    edge_kernel<<<BATCH, 1024>>>(ef);
    {
        dim3 tb(32, 8), tg(NP / 32, BATCH);
        transpose_kernel<<<tg, tb>>>(features);
    }
    main_kernel<<<(BATCH * NP) / TP, 128, SMEM_FLOATS * sizeof(float)>>>(
        (const float*)d_in[3],  (const float*)d_in[4],  (const float*)d_in[5],
        (const float*)d_in[6],  (const float*)d_in[7],  (const float*)d_in[8],
        (const float*)d_in[9],  (const float*)d_in[10], (const float*)d_in[11],
        (const float*)d_in[12], (const float*)d_in[13], (const float*)d_in[14],
        (float*)d_out);
}

// round 4
// speedup vs baseline: 1.6733x; 1.3598x over previous
#include <cuda_runtime.h>

#define K1v 16
#define BATCH 16
#define CH 32
#define NP 4096
#define EDG (NP*K1v)          // 65536
#define TP 32                 // points per CTA
#define RR 512                // neighbor rows per CTA
#define INVC 0.9999950000374997f  // 1/sqrt(1+1e-5)

// Scratch (no cudaMalloc allowed)
__device__ int   g_idx[BATCH*NP*K1v];     // 4 MB
__device__ float g_featT[BATCH*NP*CH];    // 8 MB (B,P,C)
__device__ int   g_broken[BATCH];

typedef unsigned long long u64;

__device__ __forceinline__ u64 fma2(u64 a, u64 b, u64 c) {
    u64 d;
    asm("fma.rn.f32x2 %0, %1, %2, %3;" : "=l"(d) : "l"(a), "l"(b), "l"(c));
    return d;
}
__device__ __forceinline__ u64 pack2(float x, float y) {
    u64 d;
    asm("mov.b64 %0, {%1, %2};" : "=l"(d) : "f"(x), "f"(y));
    return d;
}
__device__ __forceinline__ void unpack2(u64 v, float& x, float& y) {
    asm("mov.b64 {%0, %1}, %2;" : "=f"(x), "=f"(y) : "l"(v));
}

// ---------------------------------------------------------------------------
// Edge preprocessing (parallel): reset -> defaults+first-break -> scatter
// ---------------------------------------------------------------------------
__global__ void reset_kernel() {
    if (threadIdx.x < BATCH) g_broken[threadIdx.x] = EDG;
}

__global__ void prep_kernel(const int* __restrict__ ef) {
    int t = blockIdx.x * blockDim.x + threadIdx.x;   // over BATCH*EDG
    if (t >= BATCH * EDG) return;
    g_idx[t] = NP - K1v + (t & 15);                  // default idx0
    int b = t >> 16;                                 // EDG = 65536
    int e = t & (EDG - 1);
    const int* pf = ef + (size_t)b * 2 * EDG;
    if (e > 0) {
        int v = pf[e];
        if (v == 0 && pf[e - 1] != 0) atomicMin(&g_broken[b], e);
    }
}

__global__ void scatter_kernel(const int* __restrict__ ef) {
    const int b  = blockIdx.y;
    const int e0 = blockIdx.x * 256;
    const int t  = threadIdx.x;
    const int e  = e0 + t;
    const int* __restrict__ pf = ef + (size_t)b * 2 * EDG;
    const int* __restrict__ tg = pf + EDG;

    __shared__ int s[272];
    for (int i = t; i < 272; i += 256) {
        int src = e0 - 16 + i;
        s[i] = (src >= 0) ? pf[src] : -1;
    }
    __syncthreads();

    int v = s[t + 16];
    // backscan up to 15 for run start (runs longer than 16 -> invalid)
    int j = 0, m = e, si = t + 16;
    while (m > 0 && j < 16 && s[si - 1] == v) { m--; si--; j++; }
    if (j < 16 && e < g_broken[b] && (unsigned)v < (unsigned)NP)
        g_idx[(((size_t)b * NP + v) << 4) + j] = tg[e];
}

// ---------------------------------------------------------------------------
// Transpose features (B,C,P) -> (B,P,C)
// ---------------------------------------------------------------------------
__global__ void transpose_kernel(const float* __restrict__ f) {
    __shared__ float tile[32][33];
    int b  = blockIdx.y;
    int p0 = blockIdx.x * 32;
    int tx = threadIdx.x, ty = threadIdx.y;  // (32, 8)
    #pragma unroll
    for (int i = 0; i < 32; i += 8)
        tile[ty + i][tx] = f[((size_t)b * CH + ty + i) * NP + p0 + tx];
    __syncthreads();
    #pragma unroll
    for (int i = 0; i < 32; i += 8)
        g_featT[((size_t)b * NP + p0 + ty + i) * CH + tx] = tile[tx][ty + i];
}

// ---------------------------------------------------------------------------
// GEMM stage: 128 threads, thread tile 8o x 16r (4 groups of 4 contiguous rows).
// Warp covers 32o x 128r. Lane = oi*8 + ri. Conflict-free LDS/STS.
// MODE 0: store relu(acc*s + pb0[o][pt]);  MODE 1: store relu(acc*s + b);
// MODE 2: reduce relu(acc*s + b) over rows into red[o][pt] via shfl.
// ---------------------------------------------------------------------------
template<int MODE>
__device__ __forceinline__ void gemm_stage(
    const float* __restrict__ src,   // [32][RR]
    float*       __restrict__ dst,   // [o][RR] (MODE 0/1) or red [o][32] (MODE 2)
    const float* __restrict__ Wt,    // [32][OSTR]
    int OSTR, int o0g,
    const float* __restrict__ scal, const float* __restrict__ bias,
    const float* __restrict__ pb0s,
    int warp, int ri)
{
    u64 acc[8][8];
    #pragma unroll
    for (int o = 0; o < 8; o++)
        #pragma unroll
        for (int j = 0; j < 8; j++) acc[o][j] = 0ull;

    const float* xbase = src + warp * 128 + ri * 4;

    #pragma unroll 8
    for (int k = 0; k < 32; k++) {
        const float* wrow = Wt + k * OSTR + o0g;
        float4 w0 = *(const float4*)(wrow);
        float4 w1 = *(const float4*)(wrow + 4);
        u64 wd[8] = { pack2(w0.x,w0.x), pack2(w0.y,w0.y), pack2(w0.z,w0.z), pack2(w0.w,w0.w),
                      pack2(w1.x,w1.x), pack2(w1.y,w1.y), pack2(w1.z,w1.z), pack2(w1.w,w1.w) };
        u64 xp[8];
        #pragma unroll
        for (int g = 0; g < 4; g++) {
            float4 x = *(const float4*)(xbase + k * RR + g * 32);
            xp[2*g]   = pack2(x.x, x.y);
            xp[2*g+1] = pack2(x.z, x.w);
        }
        #pragma unroll
        for (int o = 0; o < 8; o++)
            #pragma unroll
            for (int j = 0; j < 8; j++)
                acc[o][j] = fma2(wd[o], xp[j], acc[o][j]);
    }

    const int ptbase = warp * 8 + (ri >> 2);

    #pragma unroll
    for (int o = 0; o < 8; o++) {
        int og = o0g + o;
        float s = scal[og];
        if (MODE == 2) {
            float bv = bias[og];
            #pragma unroll
            for (int g = 0; g < 4; g++) {
                float h0, h1, h2, h3;
                unpack2(acc[o][2*g],   h0, h1);
                unpack2(acc[o][2*g+1], h2, h3);
                float pa = fmaxf(fmaf(h0, s, bv), 0.f) + fmaxf(fmaf(h1, s, bv), 0.f)
                         + fmaxf(fmaf(h2, s, bv), 0.f) + fmaxf(fmaf(h3, s, bv), 0.f);
                pa += __shfl_xor_sync(0xffffffffu, pa, 1);
                pa += __shfl_xor_sync(0xffffffffu, pa, 2);
                if ((ri & 3) == 0)
                    dst[og * 32 + ptbase + g * 2] = pa;
            }
        } else {
            #pragma unroll
            for (int g = 0; g < 4; g++) {
                float bv = (MODE == 0) ? pb0s[og * 32 + ptbase + g * 2] : bias[og];
                float h0, h1, h2, h3;
                unpack2(acc[o][2*g],   h0, h1);
                unpack2(acc[o][2*g+1], h2, h3);
                h0 = fmaxf(fmaf(h0, s, bv), 0.f);
                h1 = fmaxf(fmaf(h1, s, bv), 0.f);
                h2 = fmaxf(fmaf(h2, s, bv), 0.f);
                h3 = fmaxf(fmaf(h3, s, bv), 0.f);
                *(float4*)(dst + og * RR + warp * 128 + g * 32 + ri * 4)
                    = make_float4(h0, h1, h2, h3);
            }
        }
    }
}

// ---------------------------------------------------------------------------
// Main kernel. Dynamic smem layout (float offsets):
//   0     sWt0l[32c][32o]   1024  sWt0h   2048  sWt1   3072  sWt2[32c][64o]
//   5120  sWtc[32c][64o]    7168  ss0,sb0,ss1,sb1 (32 ea)
//   7296  ss2,sb2,ssc,sbc (64 ea)         7552  CF[32c][32pt]
//   8576  pb0s[32o][32pt]   9600  red[64o][32pt]
//   11648 XA[32][512]       28032 XB[32][512]   -> 44416 floats (173.5 KB)
// ---------------------------------------------------------------------------
#define SMEM_FLOATS 44416

__global__ void __launch_bounds__(128) main_kernel(
    const float* __restrict__ W0, const float* __restrict__ g0, const float* __restrict__ bb0,
    const float* __restrict__ W1, const float* __restrict__ g1, const float* __restrict__ bb1,
    const float* __restrict__ W2, const float* __restrict__ g2, const float* __restrict__ bb2,
    const float* __restrict__ SW, const float* __restrict__ sg, const float* __restrict__ sb,
    float* __restrict__ out)
{
    extern __shared__ float sm[];
    float* sWt0l = sm;
    float* sWt0h = sm + 1024;
    float* sWt1  = sm + 2048;
    float* sWt2  = sm + 3072;
    float* sWtc  = sm + 5120;
    float* ss0   = sm + 7168;
    float* sb0   = sm + 7200;
    float* ss1   = sm + 7232;
    float* sb1   = sm + 7264;
    float* ss2   = sm + 7296;
    float* sb2   = sm + 7360;
    float* ssc   = sm + 7424;
    float* sbc   = sm + 7488;
    float* CF    = sm + 7552;
    float* pb0s  = sm + 8576;
    float* red   = sm + 9600;
    float* XA    = sm + 11648;
    float* XB    = sm + 28032;

    const int tid  = threadIdx.x;
    const int base = blockIdx.x * TP;
    const int b    = base >> 12;
    const int p0   = base & (NP - 1);

    // ---- stage weights (transposed [c][o]) and scales ----
    for (int i = tid; i < 2048; i += 128) {        // W0: (32o, 64c)
        int o = i >> 6, c = i & 63;
        float w = W0[i];
        if (c < 32) sWt0l[c * 32 + o] = w;
        else        sWt0h[(c - 32) * 32 + o] = w;
    }
    for (int i = tid; i < 1024; i += 128) {        // W1: (32o, 32c)
        int o = i >> 5, c = i & 31;
        sWt1[c * 32 + o] = W1[i];
    }
    for (int i = tid; i < 2048; i += 128) {        // W2: (64o, 32c)
        int o = i >> 5, c = i & 31;
        sWt2[c * 64 + o] = W2[i];
    }
    for (int i = tid; i < 2048; i += 128) {        // SW: (64o, 32c)
        int o = i >> 5, c = i & 31;
        sWtc[c * 64 + o] = SW[i];
    }
    if (tid < 32) { ss0[tid] = g0[tid] * INVC; sb0[tid] = bb0[tid];
                    ss1[tid] = g1[tid] * INVC; sb1[tid] = bb1[tid]; }
    else if (tid < 96) { int o = tid - 32;
                    ss2[o] = g2[o] * INVC; sb2[o] = bb2[o];
                    ssc[o] = sg[o] * INVC; sbc[o] = sb[o]; }

    const float* __restrict__ fT = g_featT + (size_t)b * NP * CH;

    // ---- stage XH: XA[c][r], r = pt*16 + k.  Thread rows {tid + 128m}. ----
    #pragma unroll
    for (int m = 0; m < 4; m++) {
        int r  = tid + m * 128;
        int pt = r >> 4;
        int k  = r & 15;
        int q  = g_idx[(((size_t)b * NP + p0 + pt) << 4) + k];
        const float4* qp = (const float4*)(fT + (size_t)q * CH);
        const float4* pp = (const float4*)(fT + (size_t)(p0 + pt) * CH);
        #pragma unroll
        for (int i = 0; i < 8; i++) {
            float4 aq = qp[i], av = pp[i];
            XA[(4*i+0) * RR + r] = aq.x - av.x;
            XA[(4*i+1) * RR + r] = aq.y - av.y;
            XA[(4*i+2) * RR + r] = aq.z - av.z;
            XA[(4*i+3) * RR + r] = aq.w - av.w;
        }
    }

    // ---- stage CF[c][pt] ----
    if (tid < TP) {
        const float4* pp = (const float4*)(fT + (size_t)(p0 + tid) * CH);
        #pragma unroll
        for (int i = 0; i < 8; i++) {
            float4 v = pp[i];
            CF[(4*i+0) * TP + tid] = v.x;
            CF[(4*i+1) * TP + tid] = v.y;
            CF[(4*i+2) * TP + tid] = v.z;
            CF[(4*i+3) * TP + tid] = v.w;
        }
    }
    __syncthreads();

    // ---- pb0[o][pt] = (W0l . cf)*ss0 + sb0 ----
    {
        int og = (tid & 3) * 8;
        int pt = tid >> 2;
        float a[8];
        #pragma unroll
        for (int j = 0; j < 8; j++) a[j] = 0.f;
        #pragma unroll
        for (int c = 0; c < 32; c++) {
            float4 w0 = *(const float4*)(sWt0l + c * 32 + og);
            float4 w1 = *(const float4*)(sWt0l + c * 32 + og + 4);
            float cf = CF[c * TP + pt];
            a[0] = fmaf(w0.x, cf, a[0]); a[1] = fmaf(w0.y, cf, a[1]);
            a[2] = fmaf(w0.z, cf, a[2]); a[3] = fmaf(w0.w, cf, a[3]);
            a[4] = fmaf(w1.x, cf, a[4]); a[5] = fmaf(w1.y, cf, a[5]);
            a[6] = fmaf(w1.z, cf, a[6]); a[7] = fmaf(w1.w, cf, a[7]);
        }
        #pragma unroll
        for (int j = 0; j < 8; j++)
            pb0s[(og + j) * TP + pt] = fmaf(a[j], ss0[og + j], sb0[og + j]);
    }
    __syncthreads();

    const int warp = tid >> 5;
    const int lane = tid & 31;
    const int oi   = lane >> 3;   // 0..3
    const int ri   = lane & 7;    // 0..7

    gemm_stage<0>(XA, XB, sWt0h, 32, oi * 8, ss0, sb0, pb0s, warp, ri);
    __syncthreads();
    gemm_stage<1>(XB, XA, sWt1, 32, oi * 8, ss1, sb1, pb0s, warp, ri);
    __syncthreads();
    gemm_stage<2>(XA, red, sWt2, 64, oi * 8,      ss2, sb2, pb0s, warp, ri);
    gemm_stage<2>(XA, red, sWt2, 64, 32 + oi * 8, ss2, sb2, pb0s, warp, ri);
    __syncthreads();

    // ---- shortcut + mean + final relu ----
    {
        int pt  = tid & 31;
        int og0 = (tid >> 5) * 16;
        float a[16];
        #pragma unroll
        for (int j = 0; j < 16; j++) a[j] = 0.f;
        #pragma unroll
        for (int c = 0; c < 32; c++) {
            float cf = CF[c * TP + pt];
            #pragma unroll
            for (int j4 = 0; j4 < 4; j4++) {
                float4 w = *(const float4*)(sWtc + c * 64 + og0 + j4 * 4);
                a[j4*4+0] = fmaf(w.x, cf, a[j4*4+0]);
                a[j4*4+1] = fmaf(w.y, cf, a[j4*4+1]);
                a[j4*4+2] = fmaf(w.z, cf, a[j4*4+2]);
                a[j4*4+3] = fmaf(w.w, cf, a[j4*4+3]);
            }
        }
        #pragma unroll
        for (int j = 0; j < 16; j++) {
            int o = og0 + j;
            float v = fmaf(a[j], ssc[o], sbc[o]) + red[o * 32 + pt] * (1.0f / 16.0f);
            out[((size_t)b * 64 + o) * NP + p0 + pt] = fmaxf(v, 0.f);
        }
    }
}

// ---------------------------------------------------------------------------
extern "C" void kernel_launch(void* const* d_in, const int* in_sizes, int n_in,
                              void* d_out, int out_size)
{
    (void)in_sizes; (void)n_in; (void)out_size;
    const float* features = (const float*)d_in[1];
    const int*   ef       = (const int*)d_in[2];

    static bool attr_set = false;
    if (!attr_set) {
        cudaFuncSetAttribute(main_kernel,
                             cudaFuncAttributeMaxDynamicSharedMemorySize,
                             SMEM_FLOATS * (int)sizeof(float));
        attr_set = true;
    }

    reset_kernel<<<1, 32>>>();
    prep_kernel<<<(BATCH * EDG) / 256, 256>>>(ef);
    {
        dim3 tg(EDG / 256, BATCH);
        scatter_kernel<<<tg, 256>>>(ef);
    }
    {
        dim3 tb(32, 8), tg(NP / 32, BATCH);
        transpose_kernel<<<tg, tb>>>(features);
    }
    main_kernel<<<(BATCH * NP) / TP, 128, SMEM_FLOATS * sizeof(float)>>>(
        (const float*)d_in[3],  (const float*)d_in[4],  (const float*)d_in[5],
        (const float*)d_in[6],  (const float*)d_in[7],  (const float*)d_in[8],
        (const float*)d_in[9],  (const float*)d_in[10], (const float*)d_in[11],
        (const float*)d_in[12], (const float*)d_in[13], (const float*)d_in[14],
        (float*)d_out);
}

// round 5
// speedup vs baseline: 1.8603x; 1.1117x over previous
#include <cuda_runtime.h>

#define K1v 16
#define BATCH 16
#define CH 32
#define NP 4096
#define EDG (NP*K1v)          // 65536
#define TP 16                 // points per CTA
#define RR 256                // neighbor rows per CTA
#define INVC 0.9999950000374997f  // 1/sqrt(1+1e-5)

// Scratch (no cudaMalloc allowed)
__device__ int   g_idx[BATCH*NP*K1v];     // 4 MB
__device__ float g_featT[BATCH*NP*CH];    // 8 MB (B,P,C)
__device__ int   g_broken[BATCH];

typedef unsigned long long u64;

__device__ __forceinline__ u64 fma2(u64 a, u64 b, u64 c) {
    u64 d;
    asm("fma.rn.f32x2 %0, %1, %2, %3;" : "=l"(d) : "l"(a), "l"(b), "l"(c));
    return d;
}
__device__ __forceinline__ u64 pack2(float x, float y) {
    u64 d;
    asm("mov.b64 %0, {%1, %2};" : "=l"(d) : "f"(x), "f"(y));
    return d;
}
__device__ __forceinline__ void unpack2(u64 v, float& x, float& y) {
    asm("mov.b64 {%0, %1}, %2;" : "=f"(x), "=f"(y) : "l"(v));
}

// ---------------------------------------------------------------------------
// Edge preprocessing (parallel): reset -> defaults+first-break -> scatter
// ---------------------------------------------------------------------------
__global__ void reset_kernel() {
    if (threadIdx.x < BATCH) g_broken[threadIdx.x] = EDG;
}

__global__ void prep_kernel(const int* __restrict__ ef) {
    int t = blockIdx.x * blockDim.x + threadIdx.x;   // over BATCH*EDG
    if (t >= BATCH * EDG) return;
    g_idx[t] = NP - K1v + (t & 15);                  // default idx0
    int b = t >> 16;                                 // EDG = 65536
    int e = t & (EDG - 1);
    const int* pf = ef + (size_t)b * 2 * EDG;
    if (e > 0) {
        int v = pf[e];
        if (v == 0 && pf[e - 1] != 0) atomicMin(&g_broken[b], e);
    }
}

__global__ void scatter_kernel(const int* __restrict__ ef) {
    const int b  = blockIdx.y;
    const int e0 = blockIdx.x * 256;
    const int t  = threadIdx.x;
    const int e  = e0 + t;
    const int* __restrict__ pf = ef + (size_t)b * 2 * EDG;
    const int* __restrict__ tg = pf + EDG;

    __shared__ int s[272];
    for (int i = t; i < 272; i += 256) {
        int src = e0 - 16 + i;
        s[i] = (src >= 0) ? pf[src] : -1;
    }
    __syncthreads();

    int v = s[t + 16];
    int j = 0, m = e, si = t + 16;
    while (m > 0 && j < 16 && s[si - 1] == v) { m--; si--; j++; }
    if (j < 16 && e < g_broken[b] && (unsigned)v < (unsigned)NP)
        g_idx[(((size_t)b * NP + v) << 4) + j] = tg[e];
}

// ---------------------------------------------------------------------------
// Transpose features (B,C,P) -> (B,P,C)
// ---------------------------------------------------------------------------
__global__ void transpose_kernel(const float* __restrict__ f) {
    __shared__ float tile[32][33];
    int b  = blockIdx.y;
    int p0 = blockIdx.x * 32;
    int tx = threadIdx.x, ty = threadIdx.y;  // (32, 8)
    #pragma unroll
    for (int i = 0; i < 32; i += 8)
        tile[ty + i][tx] = f[((size_t)b * CH + ty + i) * NP + p0 + tx];
    __syncthreads();
    #pragma unroll
    for (int i = 0; i < 32; i += 8)
        g_featT[((size_t)b * NP + p0 + ty + i) * CH + tx] = tile[tx][ty + i];
}

// ---------------------------------------------------------------------------
// GEMM stage.  Warp covers rows [warp*64, warp*64+64), thread rows:
// r = warp*64 + g*32 + ri*4 + {0..3}, g in {0,1}.  Conflict-free phases.
// TO = 8 (G1/G2, o0 = (lane>>3)*8) or 16 (G3, o0 = (lane>>3)*16).
// MODE 0: dst[o][r] = relu(acc*s + pb0[o][pt])
// MODE 1: dst[o][r] = relu(acc*s + b[o])
// MODE 2: red[o][pt] = sum_rows relu(acc*s + b[o])   (shfl over ri&3)
// ---------------------------------------------------------------------------
template<int TO, int MODE>
__device__ __forceinline__ void gemm_stage(
    const float* __restrict__ src,   // [32][RR]
    float*       __restrict__ dst,
    const float* __restrict__ Wt,    // [32][OSTR]
    int OSTR, int o0,
    const float* __restrict__ scal, const float* __restrict__ bias,
    const float* __restrict__ pb0s,
    int warp, int ri)
{
    u64 acc[TO][4];
    #pragma unroll
    for (int o = 0; o < TO; o++)
        #pragma unroll
        for (int j = 0; j < 4; j++) acc[o][j] = 0ull;

    const float* xbase = src + warp * 64 + ri * 4;

    #pragma unroll 8
    for (int k = 0; k < 32; k++) {
        u64 wd[TO];
        #pragma unroll
        for (int t4 = 0; t4 < TO / 4; t4++) {
            float4 w = *(const float4*)(Wt + k * OSTR + o0 + t4 * 4);
            wd[t4*4+0] = pack2(w.x, w.x);
            wd[t4*4+1] = pack2(w.y, w.y);
            wd[t4*4+2] = pack2(w.z, w.z);
            wd[t4*4+3] = pack2(w.w, w.w);
        }
        float4 x0 = *(const float4*)(xbase + k * RR);
        float4 x1 = *(const float4*)(xbase + k * RR + 32);
        u64 xp[4] = { pack2(x0.x, x0.y), pack2(x0.z, x0.w),
                      pack2(x1.x, x1.y), pack2(x1.z, x1.w) };
        #pragma unroll
        for (int o = 0; o < TO; o++)
            #pragma unroll
            for (int j = 0; j < 4; j++)
                acc[o][j] = fma2(wd[o], xp[j], acc[o][j]);
    }

    const int ptb = warp * 4 + (ri >> 2);   // + g*2

    #pragma unroll
    for (int o = 0; o < TO; o++) {
        int og = o0 + o;
        float s = scal[og];
        if (MODE == 2) {
            float bv = bias[og];
            #pragma unroll
            for (int g = 0; g < 2; g++) {
                float h0, h1, h2, h3;
                unpack2(acc[o][g*2],   h0, h1);
                unpack2(acc[o][g*2+1], h2, h3);
                float pa = fmaxf(fmaf(h0, s, bv), 0.f) + fmaxf(fmaf(h1, s, bv), 0.f)
                         + fmaxf(fmaf(h2, s, bv), 0.f) + fmaxf(fmaf(h3, s, bv), 0.f);
                pa += __shfl_xor_sync(0xffffffffu, pa, 1);
                pa += __shfl_xor_sync(0xffffffffu, pa, 2);
                if ((ri & 3) == 0)
                    dst[og * TP + ptb + g * 2] = pa;
            }
        } else {
            #pragma unroll
            for (int g = 0; g < 2; g++) {
                float bv = (MODE == 0) ? pb0s[og * TP + ptb + g * 2] : bias[og];
                float h0, h1, h2, h3;
                unpack2(acc[o][g*2],   h0, h1);
                unpack2(acc[o][g*2+1], h2, h3);
                h0 = fmaxf(fmaf(h0, s, bv), 0.f);
                h1 = fmaxf(fmaf(h1, s, bv), 0.f);
                h2 = fmaxf(fmaf(h2, s, bv), 0.f);
                h3 = fmaxf(fmaf(h3, s, bv), 0.f);
                *(float4*)(dst + og * RR + warp * 64 + g * 32 + ri * 4)
                    = make_float4(h0, h1, h2, h3);
            }
        }
    }
}

// ---------------------------------------------------------------------------
// Main kernel, 128 threads, TP=16 points (RR=256 rows). 2 CTAs/SM.
// Only ONE block barrier (weight staging); all dataflow is warp-private.
// Dynamic smem (float offsets):
//   0     sWt0l[32c][32o]   1024 sWt0h  2048 sWt1  3072 sWt2[32c][64o]
//   5120  sWtc[32c][64o]    7168 ss0,sb0,ss1,sb1(32)  7296 ss2,sb2,ssc,sbc(64)
//   7552  CF[32c][16pt]     8064 pb0s[32o][16]  8576 red[64o][16]
//   9600  XA[32][256]       17792 XB[32][256]   -> 25984 floats (101.5 KB)
// ---------------------------------------------------------------------------
#define SMEM_FLOATS 25984

__global__ void __launch_bounds__(128, 2) main_kernel(
    const float* __restrict__ W0, const float* __restrict__ g0, const float* __restrict__ bb0,
    const float* __restrict__ W1, const float* __restrict__ g1, const float* __restrict__ bb1,
    const float* __restrict__ W2, const float* __restrict__ g2, const float* __restrict__ bb2,
    const float* __restrict__ SW, const float* __restrict__ sg, const float* __restrict__ sb,
    float* __restrict__ out)
{
    extern __shared__ float sm[];
    float* sWt0l = sm;
    float* sWt0h = sm + 1024;
    float* sWt1  = sm + 2048;
    float* sWt2  = sm + 3072;
    float* sWtc  = sm + 5120;
    float* ss0   = sm + 7168;
    float* sb0   = sm + 7200;
    float* ss1   = sm + 7232;
    float* sb1   = sm + 7264;
    float* ss2   = sm + 7296;
    float* sb2   = sm + 7360;
    float* ssc   = sm + 7424;
    float* sbc   = sm + 7488;
    float* CF    = sm + 7552;
    float* pb0s  = sm + 8064;
    float* red   = sm + 8576;
    float* XA    = sm + 9600;
    float* XB    = sm + 17792;

    const int tid  = threadIdx.x;
    const int base = blockIdx.x * TP;
    const int b    = base >> 12;
    const int p0   = base & (NP - 1);

    // ---- stage weights (transposed [c][o]) and scales (block-cooperative) ----
    for (int i = tid; i < 2048; i += 128) {        // W0: (32o, 64c)
        int o = i >> 6, c = i & 63;
        float w = W0[i];
        if (c < 32) sWt0l[c * 32 + o] = w;
        else        sWt0h[(c - 32) * 32 + o] = w;
    }
    for (int i = tid; i < 1024; i += 128) {        // W1
        int o = i >> 5, c = i & 31;
        sWt1[c * 32 + o] = W1[i];
    }
    for (int i = tid; i < 2048; i += 128) {        // W2
        int o = i >> 5, c = i & 31;
        sWt2[c * 64 + o] = W2[i];
    }
    for (int i = tid; i < 2048; i += 128) {        // SW
        int o = i >> 5, c = i & 31;
        sWtc[c * 64 + o] = SW[i];
    }
    if (tid < 32) { ss0[tid] = g0[tid] * INVC; sb0[tid] = bb0[tid];
                    ss1[tid] = g1[tid] * INVC; sb1[tid] = bb1[tid]; }
    else if (tid < 96) { int o = tid - 32;
                    ss2[o] = g2[o] * INVC; sb2[o] = bb2[o];
                    ssc[o] = sg[o] * INVC; sbc[o] = sb[o]; }

    const float* __restrict__ fT = g_featT + (size_t)b * NP * CH;

    // ---- stage CF[c][pt]: thread -> (pt = tid>>3, 4 channels) ----
    {
        int pt = tid >> 3;
        int c0 = (tid & 7) * 4;
        float4 v = *(const float4*)(fT + (size_t)(p0 + pt) * CH + c0);
        CF[(c0+0) * TP + pt] = v.x;
        CF[(c0+1) * TP + pt] = v.y;
        CF[(c0+2) * TP + pt] = v.z;
        CF[(c0+3) * TP + pt] = v.w;
    }
    __syncwarp();

    // ---- stage XH: thread handles rows 2*tid, 2*tid+1 (same pt) ----
    {
        int r0s = tid * 2;
        int pt  = r0s >> 4;
        int k0  = r0s & 15;
        const int* ipp = g_idx + (((size_t)b * NP + p0 + pt) << 4);
        int q0 = ipp[k0];
        int q1 = ipp[k0 + 1];
        const float4* qa = (const float4*)(fT + (size_t)q0 * CH);
        const float4* qb = (const float4*)(fT + (size_t)q1 * CH);
        #pragma unroll
        for (int i = 0; i < 8; i++) {
            float4 a0 = qa[i], a1 = qb[i];
            float c0v = CF[(4*i+0) * TP + pt];
            float c1v = CF[(4*i+1) * TP + pt];
            float c2v = CF[(4*i+2) * TP + pt];
            float c3v = CF[(4*i+3) * TP + pt];
            *(float2*)(XA + (4*i+0) * RR + r0s) = make_float2(a0.x - c0v, a1.x - c0v);
            *(float2*)(XA + (4*i+1) * RR + r0s) = make_float2(a0.y - c1v, a1.y - c1v);
            *(float2*)(XA + (4*i+2) * RR + r0s) = make_float2(a0.z - c2v, a1.z - c2v);
            *(float2*)(XA + (4*i+3) * RR + r0s) = make_float2(a0.w - c3v, a1.w - c3v);
        }
    }

    __syncthreads();   // the only block barrier: weights + everything staged

    // ---- pb0[o][pt]: thread -> (pt = tid>>3, 4 o-channels) ----
    {
        int pt  = tid >> 3;
        int o0p = (tid & 7) * 4;
        float a0 = 0.f, a1 = 0.f, a2 = 0.f, a3 = 0.f;
        #pragma unroll
        for (int c = 0; c < 32; c++) {
            float4 w = *(const float4*)(sWt0l + c * 32 + o0p);
            float cf = CF[c * TP + pt];
            a0 = fmaf(w.x, cf, a0); a1 = fmaf(w.y, cf, a1);
            a2 = fmaf(w.z, cf, a2); a3 = fmaf(w.w, cf, a3);
        }
        pb0s[(o0p+0) * TP + pt] = fmaf(a0, ss0[o0p+0], sb0[o0p+0]);
        pb0s[(o0p+1) * TP + pt] = fmaf(a1, ss0[o0p+1], sb0[o0p+1]);
        pb0s[(o0p+2) * TP + pt] = fmaf(a2, ss0[o0p+2], sb0[o0p+2]);
        pb0s[(o0p+3) * TP + pt] = fmaf(a3, ss0[o0p+3], sb0[o0p+3]);
    }
    __syncwarp();

    const int warp = tid >> 5;
    const int lane = tid & 31;
    const int ri   = lane & 7;
    const int oq   = lane >> 3;      // 0..3

    gemm_stage<8, 0>(XA, XB, sWt0h, 32, oq * 8,  ss0, sb0, pb0s, warp, ri);
    __syncwarp();
    gemm_stage<8, 1>(XB, XA, sWt1,  32, oq * 8,  ss1, sb1, pb0s, warp, ri);
    __syncwarp();
    gemm_stage<16, 2>(XA, red, sWt2, 64, oq * 16, ss2, sb2, pb0s, warp, ri);
    __syncwarp();

    // ---- shortcut + mean + final relu: thread -> (pt = tid>>3, 8 o) ----
    {
        int pt  = tid >> 3;
        int o0s = (tid & 7) * 8;
        float a[8];
        #pragma unroll
        for (int j = 0; j < 8; j++) a[j] = 0.f;
        #pragma unroll
        for (int c = 0; c < 32; c++) {
            float cf = CF[c * TP + pt];
            float4 w0 = *(const float4*)(sWtc + c * 64 + o0s);
            float4 w1 = *(const float4*)(sWtc + c * 64 + o0s + 4);
            a[0] = fmaf(w0.x, cf, a[0]); a[1] = fmaf(w0.y, cf, a[1]);
            a[2] = fmaf(w0.z, cf, a[2]); a[3] = fmaf(w0.w, cf, a[3]);
            a[4] = fmaf(w1.x, cf, a[4]); a[5] = fmaf(w1.y, cf, a[5]);
            a[6] = fmaf(w1.z, cf, a[6]); a[7] = fmaf(w1.w, cf, a[7]);
        }
        #pragma unroll
        for (int j = 0; j < 8; j++) {
            int o = o0s + j;
            float v = fmaf(a[j], ssc[o], sbc[o]) + red[o * TP + pt] * (1.0f / 16.0f);
            out[((size_t)b * 64 + o) * NP + p0 + pt] = fmaxf(v, 0.f);
        }
    }
}

// ---------------------------------------------------------------------------
extern "C" void kernel_launch(void* const* d_in, const int* in_sizes, int n_in,
                              void* d_out, int out_size)
{
    (void)in_sizes; (void)n_in; (void)out_size;
    const float* features = (const float*)d_in[1];
    const int*   ef       = (const int*)d_in[2];

    static bool attr_set = false;
    if (!attr_set) {
        cudaFuncSetAttribute(main_kernel,
                             cudaFuncAttributeMaxDynamicSharedMemorySize,
                             SMEM_FLOATS * (int)sizeof(float));
        attr_set = true;
    }

    reset_kernel<<<1, 32>>>();
    prep_kernel<<<(BATCH * EDG) / 256, 256>>>(ef);
    {
        dim3 tg(EDG / 256, BATCH);
        scatter_kernel<<<tg, 256>>>(ef);
    }
    {
        dim3 tb(32, 8), tg(NP / 32, BATCH);
        transpose_kernel<<<tg, tb>>>(features);
    }
    main_kernel<<<(BATCH * NP) / TP, 128, SMEM_FLOATS * sizeof(float)>>>(
        (const float*)d_in[3],  (const float*)d_in[4],  (const float*)d_in[5],
        (const float*)d_in[6],  (const float*)d_in[7],  (const float*)d_in[8],
        (const float*)d_in[9],  (const float*)d_in[10], (const float*)d_in[11],
        (const float*)d_in[12], (const float*)d_in[13], (const float*)d_in[14],
        (float*)d_out);
}